// round 7
// baseline (speedup 1.0000x reference)
#include <cuda_runtime.h>
#include <cstdint>
#include <math.h>

#define NB 32
#define NS 512
#define NI 128
#define NH 128
#define NO 32
#define NG 384   // 3*H
#define NCONS 116            // consumer CTAs (148-32)
#define FLAG_STEP 16
#define NFLAG (NS / FLAG_STEP)     // 32
#define NMTILE 256                 // m-tiles of 64 rows (16384/64)
#define NGJOB 768                  // 256 m-tiles x 3 n-tiles

// Scratch (device globals; no allocation in kernel_launch)
__device__ float g_ih[(size_t)NB * NS * NG];          // [b][s][g]
__device__ float g_coef[(size_t)NS * NB * 4 * NH];    // [s*32+b][plane][j]
__device__ float g_wT[(size_t)NH * NG];               // [i][c] = W_hh[c][i]
__device__ unsigned g_flag[NFLAG];                    // scan progress (0..32 each)
__device__ unsigned g_ihflag[NMTILE];                 // ih tile ready (0..3 each)

// ---------------- helpers ----------------
__device__ __forceinline__ float ex2f(float x) {
    float r; asm("ex2.approx.f32 %0, %1;" : "=f"(r) : "f"(x)); return r;
}
__device__ __forceinline__ float rcpf(float x) {
    float r; asm("rcp.approx.f32 %0, %1;" : "=f"(r) : "f"(x)); return r;
}
__device__ __forceinline__ float sigf(float x) {
    return rcpf(1.0f + ex2f(-1.4426950408889634f * x));
}
__device__ __forceinline__ float tanh_fast(float x) {
    float e = ex2f(2.8853900817779268f * x);   // e^{2x}
    return 1.0f - 2.0f * rcpf(e + 1.0f);
}
__device__ __forceinline__ unsigned long long pack2(float lo, float hi) {
    unsigned long long r;
    asm("mov.b64 %0, {%1,%2};" : "=l"(r)
        : "r"(__float_as_uint(lo)), "r"(__float_as_uint(hi)));
    return r;
}
__device__ __forceinline__ void unpack2(unsigned long long v, float& lo, float& hi) {
    unsigned a, b;
    asm("mov.b64 {%0,%1}, %2;" : "=r"(a), "=r"(b) : "l"(v));
    lo = __uint_as_float(a); hi = __uint_as_float(b);
}
__device__ __forceinline__ void ffma2(unsigned long long& acc,
                                      unsigned long long a, unsigned long long b) {
    asm("fma.rn.f32x2 %0, %1, %2, %0;" : "+l"(acc) : "l"(a), "l"(b));
}
__device__ __forceinline__ unsigned ld_acquire(const unsigned* p) {
    unsigned v;
    asm volatile("ld.acquire.gpu.global.b32 %0, [%1];" : "=r"(v) : "l"(p));
    return v;
}
__device__ __forceinline__ void red_add_release(unsigned* p, unsigned v) {
    asm volatile("red.release.gpu.global.add.u32 [%0], %1;" :: "l"(p), "r"(v));
}

// ---------------- init: zero flags + transpose W_hh ----------------
__global__ void __launch_bounds__(256) init_kernel(const float* __restrict__ W_hh) {
    int t = blockIdx.x * 256 + threadIdx.x;
    if (t < NFLAG) g_flag[t] = 0u;
    if (t < NMTILE) g_ihflag[t] = 0u;
    for (int o = t; o < NH * NG; o += gridDim.x * 256) {
        int i = o / NG, c = o - i * NG;
        g_wT[o] = W_hh[(size_t)c * NH + i];
    }
}

// ---------------- one ih-GEMM tile: 64(m) x 128(n), K=128 ----------------
// Threads 0..255 compute; all 384 hit the barriers.
__device__ void gemm_tile(const float* __restrict__ x, const float* __restrict__ W_ih,
                          const float* __restrict__ b_ih,
                          int m0, int n0, int tid, float* As, float* Bs)
{
    const bool act = tid < 256;
    const int tx = tid & 15;
    const int ty = tid >> 4;
    const int lm = tid >> 3;     // 0..31 for active
    const int lk = tid & 7;

    unsigned long long acc[4][4];
#pragma unroll
    for (int a = 0; a < 4; a++)
#pragma unroll
        for (int c = 0; c < 4; c++) acc[a][c] = 0ull;

    const float4* x4 = (const float4*)x;
    const float4* w4 = (const float4*)W_ih;
    float4 ra[2], rb[4];

    if (act) {
#pragma unroll
        for (int r = 0; r < 2; r++)
            ra[r] = x4[(size_t)(m0 + lm + r * 32) * 32 + lk];
#pragma unroll
        for (int r = 0; r < 4; r++)
            rb[r] = w4[(size_t)(n0 + lm + r * 32) * 32 + lk];
    }
#pragma unroll
    for (int kc = 0; kc < 4; kc++) {
        __syncthreads();
        if (act) {
#pragma unroll
            for (int r = 0; r < 2; r++)
                ((float4*)As)[tid + r * 256] = ra[r];
#pragma unroll
            for (int r = 0; r < 4; r++) {
                int n = lm + r * 32;
                Bs[(lk * 4 + 0) * 128 + n] = rb[r].x;
                Bs[(lk * 4 + 1) * 128 + n] = rb[r].y;
                Bs[(lk * 4 + 2) * 128 + n] = rb[r].z;
                Bs[(lk * 4 + 3) * 128 + n] = rb[r].w;
            }
        }
        __syncthreads();
        if (act && kc < 3) {
#pragma unroll
            for (int r = 0; r < 2; r++)
                ra[r] = x4[(size_t)(m0 + lm + r * 32) * 32 + (kc + 1) * 8 + lk];
#pragma unroll
            for (int r = 0; r < 4; r++)
                rb[r] = w4[(size_t)(n0 + lm + r * 32) * 32 + (kc + 1) * 8 + lk];
        }
        if (act) {
#pragma unroll 8
            for (int k = 0; k < 32; k++) {
                unsigned long long a2[4];
#pragma unroll
                for (int mm = 0; mm < 4; mm++) {
                    float av = As[(ty * 4 + mm) * 32 + k];
                    a2[mm] = pack2(av, av);
                }
                const ulonglong2* bp = (const ulonglong2*)(Bs + k * 128 + tx * 8);
                ulonglong2 p0 = bp[0], p1 = bp[1];
                unsigned long long b2[4] = {p0.x, p0.y, p1.x, p1.y};
#pragma unroll
                for (int mm = 0; mm < 4; mm++)
#pragma unroll
                    for (int c = 0; c < 4; c++)
                        ffma2(acc[mm][c], a2[mm], b2[c]);
            }
        }
    }
    if (act) {
#pragma unroll
        for (int mm = 0; mm < 4; mm++) {
            int m = m0 + ty * 4 + mm;
            float* orow = g_ih + (size_t)m * NG + n0 + tx * 8;
            float vals[8];
#pragma unroll
            for (int c = 0; c < 4; c++) {
                float lo, hi;
                unpack2(acc[mm][c], lo, hi);
                int n = n0 + tx * 8 + c * 2;
                vals[c * 2]     = lo + b_ih[n];
                vals[c * 2 + 1] = hi + b_ih[n + 1];
            }
            ((float4*)orow)[0] = make_float4(vals[0], vals[1], vals[2], vals[3]);
            ((float4*)orow)[1] = make_float4(vals[4], vals[5], vals[6], vals[7]);
        }
        __threadfence();
    }
    __syncthreads();
}

// ---------------- Mega kernel ----------------
__global__ void __launch_bounds__(384, 1) mega_kernel(
    const float* __restrict__ x,    const float* __restrict__ W_ih,
    const float* __restrict__ b_ih,
    const float* __restrict__ W_hh, const float* __restrict__ b_hh,
    const float* __restrict__ W_y,  const float* __restrict__ b_y,
    float* __restrict__ out)
{
    const int tid = threadIdx.x;
    __shared__ __align__(16) float smem_pool[32 * 128 + 64 * 32];  // 24 KB union

    if (blockIdx.x < NB) {
        // ================= PRODUCER: GRU scan for batch b =================
        const int b = blockIdx.x;
        const int g = tid;
        const int role = g >> 7;        // 0: r, 1: z, 2: n
        const int j = g & 127;

        float* h_sh = smem_pool;                       // [128]
        float4* rz_sh = (float4*)(smem_pool + 128);    // [128]: (r, r', z, z')

        unsigned long long w2[64];
        const unsigned long long* wrow =
            (const unsigned long long*)(W_hh + (size_t)g * NH);
#pragma unroll
        for (int k2 = 0; k2 < 64; k2++) w2[k2] = wrow[k2];
        const float bh = b_hh[g];

        if (g < NH) h_sh[g] = 0.0f;

        const float* ihp = g_ih + (size_t)b * NS * NG;
        // wait for ih chunk 0 (acquire orders the subsequent loads)
        while (ld_acquire(&g_ihflag[b * 8]) < 3u) __nanosleep(64);
        float ih_next = ihp[g];
        __syncthreads();

        for (int s = 0; s < NS; s++) {
            float ih_cur = ih_next;
            if (s + 1 < NS) {
                if (((s + 1) & 63) == 0) {
                    int mt = b * 8 + ((s + 1) >> 6);
                    while (ld_acquire(&g_ihflag[mt]) < 3u) __nanosleep(64);
                }
                ih_next = ihp[(size_t)(s + 1) * NG + g];
            }

            // hh[g] = W_hh[g,:] . h + b_hh[g]  (f32x2) — R5 form, let ptxas schedule
            unsigned long long acc[4] = {0ull, 0ull, 0ull, 0ull};
            const ulonglong2* h4 = (const ulonglong2*)h_sh;
#pragma unroll
            for (int k4 = 0; k4 < 32; k4++) {
                ulonglong2 hv = h4[k4];
                ffma2(acc[(2 * k4) & 3],     w2[2 * k4],     hv.x);
                ffma2(acc[(2 * k4 + 1) & 3], w2[2 * k4 + 1], hv.y);
            }
            float l0, h0, l1, h1, l2, h2, l3, h3;
            unpack2(acc[0], l0, h0); unpack2(acc[1], l1, h1);
            unpack2(acc[2], l2, h2); unpack2(acc[3], l3, h3);
            float sum = ((l0 + h0) + (l1 + h1)) + ((l2 + h2) + (l3 + h3)) + bh;

            const size_t cb = ((size_t)(s * NB + b)) * (4 * NH);
            if (role == 0) {
                float r = sigf(ih_cur + sum);
                *(float2*)&rz_sh[j].x = make_float2(r, r * (1.0f - r));
            } else if (role == 1) {
                float z = sigf(ih_cur + sum);
                *(float2*)&rz_sh[j].z = make_float2(z, z * (1.0f - z));
                g_coef[cb + 3 * NH + j] = z;
                if ((s & (FLAG_STEP - 1)) == FLAG_STEP - 1) __threadfence();
            }
            __syncthreads();

            if (role == 2) {
                float M = sum;
                float4 rz = rz_sh[j];      // (r, r', z, z')
                float hp = h_sh[j];
                float n = tanh_fast(ih_cur + rz.x * M);
                float c67 = (1.0f - n * n) * (1.0f - rz.z);
                g_coef[cb + j]          = rz.y * M * c67;     // cr
                g_coef[cb + NH + j]     = rz.x * c67;         // cn
                g_coef[cb + 2 * NH + j] = rz.w * (hp - n);    // cz
                h_sh[j] = n + rz.z * (hp - n);                // h_new
                if ((s & (FLAG_STEP - 1)) == FLAG_STEP - 1) __threadfence();
            }
            __syncthreads();
            if (tid == 0 && (s & (FLAG_STEP - 1)) == FLAG_STEP - 1)
                red_add_release(&g_flag[s >> 4], 1u);
        }

        // y = h_last @ W_y^T + b_y
        if (g < NO) {
            float a = b_y[g];
            const float* wy = W_y + (size_t)g * NH;
#pragma unroll
            for (int k = 0; k < NH; k++) a = fmaf(wy[k], h_sh[k], a);
            out[b * NO + g] = a;
        }
    } else {
        // ============ CONSUMER: ih-GEMM jobs, then Jacobian ============
        const int c0 = blockIdx.x - NB;     // 0..115
        float* Bs = smem_pool;              // [32*128]
        float* As = smem_pool + 32 * 128;   // [64*32]

        // --- stage 1: ih-GEMM (schunk-major so early steps finish first) ---
        for (int jb = c0; jb < NGJOB; jb += NCONS) {
            int schunk = jb / 96;
            int r = jb - schunk * 96;
            int b = r / 3;
            int ny = r - b * 3;
            int m0 = b * 512 + schunk * 64;
            gemm_tile(x, W_ih, b_ih, m0, ny * 128, tid, As, Bs);
            if (tid == 0) red_add_release(&g_ihflag[b * 8 + schunk], 1u);
        }

        // --- stage 2: Jacobian materialization ---
        const int w = tid >> 5;
        const int lane = tid & 31;
        const int j0 = lane * 4;
        float* jac = out + NB * NO;

        int scready = -1;
        for (int t = c0; t < NS * NB; t += NCONS) {
            int s = t >> 5;
            int b = t & 31;
            int sc = s >> 4;
            if (sc != scready) {
                if (tid == 0) {
                    while (ld_acquire(&g_flag[sc]) < (unsigned)NB) __nanosleep(128);
                }
                __syncthreads();
                scready = sc;
            }
            const float4* cp = (const float4*)(g_coef + (size_t)t * (4 * NH));
            float4 cr = cp[lane];
            float4 cn = cp[32 + lane];
            float4 cz = cp[64 + lane];
            float4 zz = cp[96 + lane];
            float* obase = jac + ((size_t)((NS - 1 - s) * NB + b)) * (NH * NH);
            for (int i = w; i < NH; i += 12) {
                const float4* wp = (const float4*)(g_wT + (size_t)i * NG);
                float4 wr = wp[lane];          // W_hh[j, i]
                float4 wz = wp[32 + lane];     // W_hh[H+j, i]
                float4 wn = wp[64 + lane];     // W_hh[2H+j, i]
                float4 v;
                v.x = fmaf(wr.x, cr.x, fmaf(wn.x, cn.x, wz.x * cz.x));
                v.y = fmaf(wr.y, cr.y, fmaf(wn.y, cn.y, wz.y * cz.y));
                v.z = fmaf(wr.z, cr.z, fmaf(wn.z, cn.z, wz.z * cz.z));
                v.w = fmaf(wr.w, cr.w, fmaf(wn.w, cn.w, wz.w * cz.w));
                if ((i >> 2) == lane) {        // diagonal j == i
                    int d = i & 3;
                    if (d == 0) v.x += zz.x;
                    else if (d == 1) v.y += zz.y;
                    else if (d == 2) v.z += zz.z;
                    else v.w += zz.w;
                }
                *(float4*)(obase + i * NH + j0) = v;
            }
        }
    }
}

// ---------------- launch ----------------
extern "C" void kernel_launch(void* const* d_in, const int* in_sizes, int n_in,
                              void* d_out, int out_size) {
    const float* x    = (const float*)d_in[0];
    const float* W_ih = (const float*)d_in[1];
    const float* W_hh = (const float*)d_in[2];
    const float* b_ih = (const float*)d_in[3];
    const float* b_hh = (const float*)d_in[4];
    const float* W_y  = (const float*)d_in[5];
    const float* b_y  = (const float*)d_in[6];
    float* out = (float*)d_out;

    init_kernel<<<64, 256>>>(W_hh);
    mega_kernel<<<NB + NCONS, NG>>>(x, W_ih, b_ih, W_hh, b_hh, W_y, b_y, out);
}

// round 8
// speedup vs baseline: 1.0106x; 1.0106x over previous
#include <cuda_runtime.h>
#include <cstdint>
#include <math.h>

#define NB 32
#define NS 512
#define NI 128
#define NH 128
#define NO 32
#define NG 384   // 3*H
#define NCONS 116            // consumer CTAs (148-32)
#define FLAG_STEP 8
#define NFLAG (NS / FLAG_STEP)     // 64
#define NMTILE 256                 // 32 b x 8 schunks
#define NGJOB 768                  // 256 m-tiles x 3 n-tiles

// Scratch (device globals; no allocation in kernel_launch)
__device__ float g_ih[(size_t)NB * NS * NG];          // [b][s][g]
__device__ float g_coef[(size_t)NS * NB * 4 * NH];    // [s*32+b][plane][j]
__device__ float g_wT[(size_t)NH * NG];               // [i][c] = W_hh[c][i]
__device__ unsigned g_flag[NFLAG];                    // scan progress (0..32 each)
__device__ unsigned g_ihflag[NMTILE];                 // ih tile ready (0..3 each)

// ---------------- helpers ----------------
__device__ __forceinline__ float ex2f(float x) {
    float r; asm("ex2.approx.f32 %0, %1;" : "=f"(r) : "f"(x)); return r;
}
__device__ __forceinline__ float rcpf(float x) {
    float r; asm("rcp.approx.f32 %0, %1;" : "=f"(r) : "f"(x)); return r;
}
__device__ __forceinline__ float sigf(float x) {
    return rcpf(1.0f + ex2f(-1.4426950408889634f * x));
}
__device__ __forceinline__ float tanh_fast(float x) {
    float e = ex2f(2.8853900817779268f * x);   // e^{2x}
    return 1.0f - 2.0f * rcpf(e + 1.0f);
}
__device__ __forceinline__ unsigned long long pack2(float lo, float hi) {
    unsigned long long r;
    asm("mov.b64 %0, {%1,%2};" : "=l"(r)
        : "r"(__float_as_uint(lo)), "r"(__float_as_uint(hi)));
    return r;
}
__device__ __forceinline__ void unpack2(unsigned long long v, float& lo, float& hi) {
    unsigned a, b;
    asm("mov.b64 {%0,%1}, %2;" : "=r"(a), "=r"(b) : "l"(v));
    lo = __uint_as_float(a); hi = __uint_as_float(b);
}
__device__ __forceinline__ void ffma2(unsigned long long& acc,
                                      unsigned long long a, unsigned long long b) {
    asm("fma.rn.f32x2 %0, %1, %2, %0;" : "+l"(acc) : "l"(a), "l"(b));
}
__device__ __forceinline__ unsigned long long addf2(unsigned long long a,
                                                    unsigned long long b) {
    unsigned long long r;
    asm("add.rn.f32x2 %0, %1, %2;" : "=l"(r) : "l"(a), "l"(b));
    return r;
}
__device__ __forceinline__ unsigned ld_acquire(const unsigned* p) {
    unsigned v;
    asm volatile("ld.acquire.gpu.global.b32 %0, [%1];" : "=r"(v) : "l"(p));
    return v;
}
__device__ __forceinline__ void red_add_release(unsigned* p, unsigned v) {
    asm volatile("red.release.gpu.global.add.u32 [%0], %1;" :: "l"(p), "r"(v));
}

// ---------------- init: zero flags + transpose W_hh ----------------
__global__ void __launch_bounds__(256) init_kernel(const float* __restrict__ W_hh) {
    int t = blockIdx.x * 256 + threadIdx.x;
    if (t < NFLAG) g_flag[t] = 0u;
    if (t < NMTILE) g_ihflag[t] = 0u;
    for (int o = t; o < NH * NG; o += gridDim.x * 256) {
        int i = o / NG, c = o - i * NG;
        g_wT[o] = W_hh[(size_t)c * NH + i];
    }
}

// ---------------- one ih-GEMM tile: 64(m) x 128(n), K=128 ----------------
__device__ void gemm_tile(const float* __restrict__ x, const float* __restrict__ W_ih,
                          const float* __restrict__ b_ih,
                          int m0, int n0, int tid, float* As, float* Bs)
{
    const bool act = tid < 256;
    const int tx = tid & 15;
    const int ty = tid >> 4;
    const int lm = tid >> 3;
    const int lk = tid & 7;

    unsigned long long acc[4][4];
#pragma unroll
    for (int a = 0; a < 4; a++)
#pragma unroll
        for (int c = 0; c < 4; c++) acc[a][c] = 0ull;

    const float4* x4 = (const float4*)x;
    const float4* w4 = (const float4*)W_ih;
    float4 ra[2], rb[4];

    if (act) {
#pragma unroll
        for (int r = 0; r < 2; r++)
            ra[r] = x4[(size_t)(m0 + lm + r * 32) * 32 + lk];
#pragma unroll
        for (int r = 0; r < 4; r++)
            rb[r] = w4[(size_t)(n0 + lm + r * 32) * 32 + lk];
    }
#pragma unroll
    for (int kc = 0; kc < 4; kc++) {
        __syncthreads();
        if (act) {
#pragma unroll
            for (int r = 0; r < 2; r++)
                ((float4*)As)[tid + r * 256] = ra[r];
#pragma unroll
            for (int r = 0; r < 4; r++) {
                int n = lm + r * 32;
                Bs[(lk * 4 + 0) * 128 + n] = rb[r].x;
                Bs[(lk * 4 + 1) * 128 + n] = rb[r].y;
                Bs[(lk * 4 + 2) * 128 + n] = rb[r].z;
                Bs[(lk * 4 + 3) * 128 + n] = rb[r].w;
            }
        }
        __syncthreads();
        if (act && kc < 3) {
#pragma unroll
            for (int r = 0; r < 2; r++)
                ra[r] = x4[(size_t)(m0 + lm + r * 32) * 32 + (kc + 1) * 8 + lk];
#pragma unroll
            for (int r = 0; r < 4; r++)
                rb[r] = w4[(size_t)(n0 + lm + r * 32) * 32 + (kc + 1) * 8 + lk];
        }
        if (act) {
#pragma unroll 8
            for (int k = 0; k < 32; k++) {
                unsigned long long a2[4];
#pragma unroll
                for (int mm = 0; mm < 4; mm++) {
                    float av = As[(ty * 4 + mm) * 32 + k];
                    a2[mm] = pack2(av, av);
                }
                const ulonglong2* bp = (const ulonglong2*)(Bs + k * 128 + tx * 8);
                ulonglong2 p0 = bp[0], p1 = bp[1];
                unsigned long long b2[4] = {p0.x, p0.y, p1.x, p1.y};
#pragma unroll
                for (int mm = 0; mm < 4; mm++)
#pragma unroll
                    for (int c = 0; c < 4; c++)
                        ffma2(acc[mm][c], a2[mm], b2[c]);
            }
        }
    }
    if (act) {
#pragma unroll
        for (int mm = 0; mm < 4; mm++) {
            int m = m0 + ty * 4 + mm;
            float* orow = g_ih + (size_t)m * NG + n0 + tx * 8;
            float vals[8];
#pragma unroll
            for (int c = 0; c < 4; c++) {
                float lo, hi;
                unpack2(acc[mm][c], lo, hi);
                int n = n0 + tx * 8 + c * 2;
                vals[c * 2]     = lo + b_ih[n];
                vals[c * 2 + 1] = hi + b_ih[n + 1];
            }
            ((float4*)orow)[0] = make_float4(vals[0], vals[1], vals[2], vals[3]);
            ((float4*)orow)[1] = make_float4(vals[4], vals[5], vals[6], vals[7]);
        }
        __threadfence();
    }
    __syncthreads();
}

// ---------------- Mega kernel ----------------
__global__ void __launch_bounds__(384, 1) mega_kernel(
    const float* __restrict__ x,    const float* __restrict__ W_ih,
    const float* __restrict__ b_ih,
    const float* __restrict__ W_hh, const float* __restrict__ b_hh,
    const float* __restrict__ W_y,  const float* __restrict__ b_y,
    float* __restrict__ out)
{
    const int tid = threadIdx.x;
    __shared__ __align__(16) float smem_pool[32 * 128 + 64 * 32];  // 24 KB union

    if (blockIdx.x < NB) {
        // ================= PRODUCER: GRU scan for batch b (R5 form) =================
        const int b = blockIdx.x;
        const int g = tid;
        const int role = g >> 7;        // 0: r, 1: z, 2: n
        const int j = g & 127;

        float* h_sh = smem_pool;                       // [128]
        float4* rz_sh = (float4*)(smem_pool + 128);    // [128]: (r, r', z, z')

        unsigned long long w2[64];
        const unsigned long long* wrow =
            (const unsigned long long*)(W_hh + (size_t)g * NH);
#pragma unroll
        for (int k2 = 0; k2 < 64; k2++) w2[k2] = wrow[k2];
        const float bh = b_hh[g];

        if (g < NH) h_sh[g] = 0.0f;

        const float* ihp = g_ih + (size_t)b * NS * NG;
        // wait for ih chunk 0 (tid0 polls, barrier publishes)
        if (tid == 0) {
            while (ld_acquire(&g_ihflag[b * 8]) < 3u) __nanosleep(64);
        }
        __syncthreads();
        float ih_next = ihp[g];

        for (int s = 0; s < NS; s++) {
            float ih_cur = ih_next;
            if (s + 1 < NS) {
                if (((s + 1) & 63) == 0) {
                    if (tid == 0) {
                        int mt = b * 8 + ((s + 1) >> 6);
                        while (ld_acquire(&g_ihflag[mt]) < 3u) __nanosleep(64);
                    }
                    __syncthreads();
                }
                ih_next = ihp[(size_t)(s + 1) * NG + g];
            }

            // hh[g] = W_hh[g,:] . h + b_hh[g]  (f32x2)
            unsigned long long acc[4] = {0ull, 0ull, 0ull, 0ull};
            const ulonglong2* h4 = (const ulonglong2*)h_sh;
#pragma unroll
            for (int k4 = 0; k4 < 32; k4++) {
                ulonglong2 hv = h4[k4];
                ffma2(acc[(2 * k4) & 3],     w2[2 * k4],     hv.x);
                ffma2(acc[(2 * k4 + 1) & 3], w2[2 * k4 + 1], hv.y);
            }
            unsigned long long t01 = addf2(acc[0], acc[1]);
            unsigned long long t23 = addf2(acc[2], acc[3]);
            unsigned long long tt  = addf2(t01, t23);
            float lo, hi;
            unpack2(tt, lo, hi);
            float sum = lo + hi + bh;

            const size_t cb = ((size_t)(s * NB + b)) * (4 * NH);
            if (role == 0) {
                float r = sigf(ih_cur + sum);
                *(float2*)&rz_sh[j].x = make_float2(r, r * (1.0f - r));
            } else if (role == 1) {
                float z = sigf(ih_cur + sum);
                *(float2*)&rz_sh[j].z = make_float2(z, z * (1.0f - z));
                g_coef[cb + 3 * NH + j] = z;
                if ((s & (FLAG_STEP - 1)) == FLAG_STEP - 1) __threadfence();
            }
            __syncthreads();

            if (role == 2) {
                float M = sum;
                float4 rz = rz_sh[j];      // (r, r', z, z')
                float hp = h_sh[j];
                float n = tanh_fast(ih_cur + rz.x * M);
                float c67 = (1.0f - n * n) * (1.0f - rz.z);
                g_coef[cb + j]          = rz.y * M * c67;     // cr
                g_coef[cb + NH + j]     = rz.x * c67;         // cn
                g_coef[cb + 2 * NH + j] = rz.w * (hp - n);    // cz
                h_sh[j] = n + rz.z * (hp - n);                // h_new
                if ((s & (FLAG_STEP - 1)) == FLAG_STEP - 1) __threadfence();
            }
            __syncthreads();
            if (tid == 0 && (s & (FLAG_STEP - 1)) == FLAG_STEP - 1)
                red_add_release(&g_flag[s >> 3], 1u);
        }

        // y = h_last @ W_y^T + b_y
        if (g < NO) {
            float a = b_y[g];
            const float* wy = W_y + (size_t)g * NH;
#pragma unroll
            for (int k = 0; k < NH; k++) a = fmaf(wy[k], h_sh[k], a);
            out[b * NO + g] = a;
        }
    } else {
        // ============ CONSUMER: ih-GEMM jobs, then register-pinned Jacobian ============
        const int c0 = blockIdx.x - NB;     // 0..115
        float* Bs = smem_pool;              // [32*128]
        float* As = smem_pool + 32 * 128;   // [64*32]

        // --- stage 1: ih-GEMM (schunk-major so early steps finish first) ---
        for (int jb = c0; jb < NGJOB; jb += NCONS) {
            int schunk = jb / 96;
            int r = jb - schunk * 96;
            int b = r / 3;
            int ny = r - b * 3;
            int m0 = b * 512 + schunk * 64;
            gemm_tile(x, W_ih, b_ih, m0, ny * 128, tid, As, Bs);
            if (tid == 0) red_add_release(&g_ihflag[b * 8 + schunk], 1u);
        }

        // --- stage 2: Jacobian, W pinned in registers per (iset, jq) ---
        const int jq = tid & 31;            // j-quad: j = jq*4 .. jq*4+3
        const int iset = tid >> 5;          // 0..11; i = iset + 12k
        const int kn = (NH - iset + 11) / 12;   // 11 (iset<8) or 10

        float4 wr[11], wz[11], wn[11];
#pragma unroll
        for (int k = 0; k < 11; k++) {
            if (k < kn) {
                int i = iset + 12 * k;
                const float4* wp = (const float4*)(g_wT + (size_t)i * NG);
                wr[k] = wp[jq];             // W_hh[j, i]
                wz[k] = wp[32 + jq];        // W_hh[H+j, i]
                wn[k] = wp[64 + jq];        // W_hh[2H+j, i]
            }
        }

        float* jac = out + NB * NO;
        int scready = -1;
        for (int t = c0; t < NS * NB; t += NCONS) {
            int s = t >> 5;
            int b = t & 31;
            int sc = s >> 3;
            if (sc != scready) {
                if (tid == 0) {
                    while (ld_acquire(&g_flag[sc]) < (unsigned)NB) __nanosleep(128);
                }
                __syncthreads();
                scready = sc;
            }
            const float4* cp = (const float4*)(g_coef + (size_t)t * (4 * NH));
            float4 cr = cp[jq];
            float4 cn = cp[32 + jq];
            float4 cz = cp[64 + jq];
            float4 zz = cp[96 + jq];
            float* obase = jac + ((size_t)((NS - 1 - s) * NB + b)) * (NH * NH)
                         + jq * 4;
#pragma unroll
            for (int k = 0; k < 11; k++) {
                if (k < kn) {
                    int i = iset + 12 * k;
                    float4 v;
                    v.x = fmaf(wr[k].x, cr.x, fmaf(wn[k].x, cn.x, wz[k].x * cz.x));
                    v.y = fmaf(wr[k].y, cr.y, fmaf(wn[k].y, cn.y, wz[k].y * cz.y));
                    v.z = fmaf(wr[k].z, cr.z, fmaf(wn[k].z, cn.z, wz[k].z * cz.z));
                    v.w = fmaf(wr[k].w, cr.w, fmaf(wn[k].w, cn.w, wz[k].w * cz.w));
                    if ((i >> 2) == jq) {   // diagonal j == i
                        int d = i & 3;
                        if (d == 0) v.x += zz.x;
                        else if (d == 1) v.y += zz.y;
                        else if (d == 2) v.z += zz.z;
                        else v.w += zz.w;
                    }
                    *(float4*)(obase + i * NH) = v;
                }
            }
        }
    }
}

// ---------------- launch ----------------
extern "C" void kernel_launch(void* const* d_in, const int* in_sizes, int n_in,
                              void* d_out, int out_size) {
    const float* x    = (const float*)d_in[0];
    const float* W_ih = (const float*)d_in[1];
    const float* W_hh = (const float*)d_in[2];
    const float* b_ih = (const float*)d_in[3];
    const float* b_hh = (const float*)d_in[4];
    const float* W_y  = (const float*)d_in[5];
    const float* b_y  = (const float*)d_in[6];
    float* out = (float*)d_out;

    init_kernel<<<64, 256>>>(W_hh);
    mega_kernel<<<NB + NCONS, NG>>>(x, W_ih, b_ih, W_hh, b_hh, W_y, b_y, out);
}

// round 9
// speedup vs baseline: 1.1519x; 1.1398x over previous
#include <cuda_runtime.h>
#include <cstdint>
#include <math.h>

#define NB 32
#define NS 512
#define NI 128
#define NH 128
#define NO 32
#define NG 384   // 3*H
#define NCONS 116            // consumer CTAs in mega kernel (148-32)
#define FLAG_STEP 8
#define NFLAG (NS / FLAG_STEP)

// Scratch (device globals; no allocation in kernel_launch)
__device__ float g_ih[(size_t)NB * NS * NG];          // [b][s][g]
__device__ float g_coef[(size_t)NS * NB * 4 * NH];    // [s*32+b][plane][j]
__device__ float g_wT[(size_t)NH * NG];               // [i][c] = W_hh[c][i]
__device__ unsigned g_flag[NFLAG];                    // per-8-step completion counters

// ---------------- helpers ----------------
__device__ __forceinline__ float ex2f(float x) {
    float r; asm("ex2.approx.f32 %0, %1;" : "=f"(r) : "f"(x)); return r;
}
__device__ __forceinline__ float rcpf(float x) {
    float r; asm("rcp.approx.f32 %0, %1;" : "=f"(r) : "f"(x)); return r;
}
__device__ __forceinline__ float sigf(float x) {
    return rcpf(1.0f + ex2f(-1.4426950408889634f * x));
}
__device__ __forceinline__ float tanh_fast(float x) {
    float e = ex2f(2.8853900817779268f * x);   // e^{2x}
    return 1.0f - 2.0f * rcpf(e + 1.0f);
}
__device__ __forceinline__ unsigned long long pack2(float lo, float hi) {
    unsigned long long r;
    asm("mov.b64 %0, {%1,%2};" : "=l"(r)
        : "r"(__float_as_uint(lo)), "r"(__float_as_uint(hi)));
    return r;
}
__device__ __forceinline__ void unpack2(unsigned long long v, float& lo, float& hi) {
    unsigned a, b;
    asm("mov.b64 {%0,%1}, %2;" : "=r"(a), "=r"(b) : "l"(v));
    lo = __uint_as_float(a); hi = __uint_as_float(b);
}
__device__ __forceinline__ void ffma2(unsigned long long& acc,
                                      unsigned long long a, unsigned long long b) {
    asm("fma.rn.f32x2 %0, %1, %2, %0;" : "+l"(acc) : "l"(a), "l"(b));
}
__device__ __forceinline__ unsigned ld_acquire(const unsigned* p) {
    unsigned v;
    asm volatile("ld.acquire.gpu.global.b32 %0, [%1];" : "=r"(v) : "l"(p));
    return v;
}
__device__ __forceinline__ void red_add_release(unsigned* p, unsigned v) {
    asm volatile("red.release.gpu.global.add.u32 [%0], %1;" :: "l"(p), "r"(v));
}

// ---------------- init: zero flags + transpose W_hh ----------------
__global__ void __launch_bounds__(256) init_kernel(const float* __restrict__ W_hh) {
    int t = blockIdx.x * 256 + threadIdx.x;
    if (t < NFLAG) g_flag[t] = 0u;
    for (int o = t; o < NH * NG; o += gridDim.x * 256) {
        int i = o / NG, c = o - i * NG;
        g_wT[o] = W_hh[(size_t)c * NH + i];
    }
}

// ---------------- Phase A: ih = x @ W_ih^T + b_ih ----------------
// M=16384, N=384, K=128. CTA tile 128(m) x 64(n), 256 threads, K in 4 chunks
// of 32, register double-buffered loads. Thread = 4m x 8n -> per k-iter only
// ~6 smem wavefronts per warp (vs 12 before): compute-bound, not crossbar-bound.
__global__ void __launch_bounds__(256) ih_gemm_kernel(
    const float* __restrict__ x, const float* __restrict__ W_ih,
    const float* __restrict__ b_ih)
{
    __shared__ __align__(16) float As[128 * 32];   // [m][k]  16 KB
    __shared__ __align__(16) float Bs[32 * 64];    // [k][n]   8 KB
    const int m0 = blockIdx.x * 128;
    const int n0 = blockIdx.y * 64;
    const int tid = threadIdx.x;
    const int tx = tid & 7;      // n-group: n = tx*8 .. tx*8+7
    const int ty = tid >> 3;     // m-group: rows ty*4 .. ty*4+3

    unsigned long long acc[4][4];
#pragma unroll
    for (int a = 0; a < 4; a++)
#pragma unroll
        for (int c = 0; c < 4; c++) acc[a][c] = 0ull;

    const float4* x4 = (const float4*)x;
    const float4* w4 = (const float4*)W_ih;
    const int lm = tid >> 3;     // reuse: 0..31
    const int lk = tid & 7;

    float4 ra[4], rb[2];
#define LOAD_CHUNK(kc)                                                          \
    {                                                                           \
        _Pragma("unroll")                                                       \
        for (int r = 0; r < 4; r++)                                             \
            ra[r] = x4[(size_t)(m0 + lm + r * 32) * 32 + (kc) * 8 + lk];        \
        _Pragma("unroll")                                                       \
        for (int r = 0; r < 2; r++) {                                           \
            int idx = tid + r * 256;                                            \
            rb[r] = w4[(size_t)(n0 + (idx >> 3)) * 32 + (kc) * 8 + (idx & 7)];  \
        }                                                                       \
    }

    LOAD_CHUNK(0);
#pragma unroll
    for (int kc = 0; kc < 4; kc++) {
        __syncthreads();
        // As: [m][k] direct float4 copy (idx = m*8+kq)
#pragma unroll
        for (int r = 0; r < 4; r++)
            ((float4*)As)[(lm + r * 32) * 8 + lk] = ra[r];
        // Bs: transpose to [k][n]
#pragma unroll
        for (int r = 0; r < 2; r++) {
            int idx = tid + r * 256;
            int n = idx >> 3, kq = idx & 7;
            Bs[(kq * 4 + 0) * 64 + n] = rb[r].x;
            Bs[(kq * 4 + 1) * 64 + n] = rb[r].y;
            Bs[(kq * 4 + 2) * 64 + n] = rb[r].z;
            Bs[(kq * 4 + 3) * 64 + n] = rb[r].w;
        }
        __syncthreads();
        if (kc < 3) LOAD_CHUNK(kc + 1);
#pragma unroll 8
        for (int k = 0; k < 32; k++) {
            unsigned long long a2[4];
#pragma unroll
            for (int mm = 0; mm < 4; mm++) {
                float av = As[(ty * 4 + mm) * 32 + k];
                a2[mm] = pack2(av, av);
            }
            const ulonglong2* bp = (const ulonglong2*)(Bs + k * 64 + tx * 8);
            ulonglong2 p0 = bp[0], p1 = bp[1];
            unsigned long long b2[4] = {p0.x, p0.y, p1.x, p1.y};
#pragma unroll
            for (int mm = 0; mm < 4; mm++)
#pragma unroll
                for (int c = 0; c < 4; c++)
                    ffma2(acc[mm][c], a2[mm], b2[c]);
        }
    }
#undef LOAD_CHUNK
    // Epilogue: bias + store 8 contiguous floats per (thread, m-row)
#pragma unroll
    for (int mm = 0; mm < 4; mm++) {
        int m = m0 + ty * 4 + mm;
        float* orow = g_ih + (size_t)m * NG + n0 + tx * 8;
        float vals[8];
#pragma unroll
        for (int c = 0; c < 4; c++) {
            float lo, hi;
            unpack2(acc[mm][c], lo, hi);
            int n = n0 + tx * 8 + c * 2;
            vals[c * 2]     = lo + b_ih[n];
            vals[c * 2 + 1] = hi + b_ih[n + 1];
        }
        ((float4*)orow)[0] = make_float4(vals[0], vals[1], vals[2], vals[3]);
        ((float4*)orow)[1] = make_float4(vals[4], vals[5], vals[6], vals[7]);
    }
}

// ---------------- Mega kernel: scan producers (CTA 0..31) + jac consumers ----------------
// R5 structure verbatim (known-best scan pacing).
__global__ void __launch_bounds__(384, 1) mega_kernel(
    const float* __restrict__ W_hh, const float* __restrict__ b_hh,
    const float* __restrict__ W_y,  const float* __restrict__ b_y,
    float* __restrict__ out)
{
    const int tid = threadIdx.x;

    if (blockIdx.x < NB) {
        // ================= PRODUCER: GRU scan for batch b =================
        const int b = blockIdx.x;
        const int g = tid;
        const int role = g >> 7;        // 0: r, 1: z, 2: n
        const int j = g & 127;

        __shared__ __align__(16) float h_sh[NH];
        __shared__ __align__(8) float2 rp_sh[NH];   // (r, r*(1-r))
        __shared__ __align__(8) float2 zp_sh[NH];   // (z, z*(1-z))

        unsigned long long w2[64];
        const unsigned long long* wrow =
            (const unsigned long long*)(W_hh + (size_t)g * NH);
#pragma unroll
        for (int k2 = 0; k2 < 64; k2++) w2[k2] = wrow[k2];
        const float bh = b_hh[g];

        if (g < NH) h_sh[g] = 0.0f;

        const float* ihp = g_ih + (size_t)b * NS * NG;
        float ih_next = ihp[g];           // s = 0, own gate value (coalesced)
        __syncthreads();

        for (int s = 0; s < NS; s++) {
            float ih_cur = ih_next;
            if (s + 1 < NS) ih_next = ihp[(size_t)(s + 1) * NG + g];

            // hh[g] = W_hh[g,:] . h + b_hh[g]  (f32x2)
            unsigned long long acc[4] = {0ull, 0ull, 0ull, 0ull};
            const ulonglong2* h4 = (const ulonglong2*)h_sh;
#pragma unroll
            for (int k4 = 0; k4 < 32; k4++) {
                ulonglong2 hv = h4[k4];
                ffma2(acc[(2 * k4) & 3],     w2[2 * k4],     hv.x);
                ffma2(acc[(2 * k4 + 1) & 3], w2[2 * k4 + 1], hv.y);
            }
            float l0, h0, l1, h1, l2, h2, l3, h3;
            unpack2(acc[0], l0, h0); unpack2(acc[1], l1, h1);
            unpack2(acc[2], l2, h2); unpack2(acc[3], l3, h3);
            float sum = ((l0 + h0) + (l1 + h1)) + ((l2 + h2) + (l3 + h3)) + bh;

            const size_t cb = ((size_t)(s * NB + b)) * (4 * NH);
            if (role == 0) {
                float r = sigf(ih_cur + sum);
                rp_sh[j] = make_float2(r, r * (1.0f - r));
            } else if (role == 1) {
                float z = sigf(ih_cur + sum);
                zp_sh[j] = make_float2(z, z * (1.0f - z));
                g_coef[cb + 3 * NH + j] = z;
                if ((s & (FLAG_STEP - 1)) == FLAG_STEP - 1) __threadfence();
            }
            __syncthreads();

            if (role == 2) {
                float M = sum;
                float2 rp = rp_sh[j];
                float2 zp = zp_sh[j];
                float hp = h_sh[j];
                float n = tanh_fast(ih_cur + rp.x * M);
                float c67 = (1.0f - n * n) * (1.0f - zp.x);
                g_coef[cb + j]          = rp.y * M * c67;     // cr
                g_coef[cb + NH + j]     = rp.x * c67;         // cn
                g_coef[cb + 2 * NH + j] = zp.y * (hp - n);    // cz
                h_sh[j] = n + zp.x * (hp - n);                // h_new
                if ((s & (FLAG_STEP - 1)) == FLAG_STEP - 1) __threadfence();
            }
            __syncthreads();
            if (g == 0 && (s & (FLAG_STEP - 1)) == FLAG_STEP - 1)
                red_add_release(&g_flag[s >> 3], 1u);
        }

        // y = h_last @ W_y^T + b_y
        if (g < NO) {
            float a = b_y[g];
            const float* wy = W_y + (size_t)g * NH;
#pragma unroll
            for (int k = 0; k < NH; k++) a = fmaf(wy[k], h_sh[k], a);
            out[b * NO + g] = a;
        }
    } else {
        // ================= CONSUMER: Jacobian materialization =================
        const int c0 = blockIdx.x - NB;     // 0..115
        const int w = tid >> 5;             // warp 0..11 -> i rows
        const int lane = tid & 31;
        const int j0 = lane * 4;
        float* jac = out + NB * NO;

        int scready = -1;
        for (int t = c0; t < NS * NB; t += NCONS) {
            int s = t >> 5;
            int b = t & 31;
            int sc = s >> 3;
            if (sc != scready) {
                if (tid == 0) {
                    while (ld_acquire(&g_flag[sc]) < (unsigned)NB) __nanosleep(128);
                }
                __syncthreads();
                scready = sc;
            }
            const float4* cp = (const float4*)(g_coef + (size_t)t * (4 * NH));
            float4 cr = cp[lane];
            float4 cn = cp[32 + lane];
            float4 cz = cp[64 + lane];
            float4 zz = cp[96 + lane];
            float* obase = jac + ((size_t)((NS - 1 - s) * NB + b)) * (NH * NH);
            for (int i = w; i < NH; i += 12) {
                const float4* wp = (const float4*)(g_wT + (size_t)i * NG);
                float4 wr = wp[lane];          // W_hh[j, i]
                float4 wz = wp[32 + lane];     // W_hh[H+j, i]
                float4 wn = wp[64 + lane];     // W_hh[2H+j, i]
                float4 v;
                v.x = fmaf(wr.x, cr.x, fmaf(wn.x, cn.x, wz.x * cz.x));
                v.y = fmaf(wr.y, cr.y, fmaf(wn.y, cn.y, wz.y * cz.y));
                v.z = fmaf(wr.z, cr.z, fmaf(wn.z, cn.z, wz.z * cz.z));
                v.w = fmaf(wr.w, cr.w, fmaf(wn.w, cn.w, wz.w * cz.w));
                if ((i >> 2) == lane) {        // diagonal j == i
                    int d = i & 3;
                    if (d == 0) v.x += zz.x;
                    else if (d == 1) v.y += zz.y;
                    else if (d == 2) v.z += zz.z;
                    else v.w += zz.w;
                }
                *(float4*)(obase + i * NH + j0) = v;
            }
        }
    }
}

// ---------------- launch ----------------
extern "C" void kernel_launch(void* const* d_in, const int* in_sizes, int n_in,
                              void* d_out, int out_size) {
    const float* x    = (const float*)d_in[0];
    const float* W_ih = (const float*)d_in[1];
    const float* W_hh = (const float*)d_in[2];
    const float* b_ih = (const float*)d_in[3];
    const float* b_hh = (const float*)d_in[4];
    const float* W_y  = (const float*)d_in[5];
    const float* b_y  = (const float*)d_in[6];
    float* out = (float*)d_out;

    init_kernel<<<64, 256>>>(W_hh);
    ih_gemm_kernel<<<dim3(128, 6), 256>>>(x, W_ih, b_ih);
    mega_kernel<<<NB + NCONS, NG>>>(W_hh, b_hh, W_y, b_y, out);
}

// round 10
// speedup vs baseline: 1.3304x; 1.1549x over previous
#include <cuda_runtime.h>
#include <cstdint>
#include <math.h>

#define NB 32
#define NS 512
#define NI 128
#define NH 128
#define NO 32
#define NG 384   // 3*H
#define NCONS 116            // consumer CTAs in mega kernel (148-32)
#define FLAG_STEP 8
#define NFLAG (NS / FLAG_STEP)

// Scratch (device globals; no allocation in kernel_launch)
__device__ float g_ih[(size_t)NB * NS * NG];          // [b][s][g]
__device__ float g_coef[(size_t)NS * NB * 4 * NH];    // [s*32+b][plane][j]
__device__ float g_wT[(size_t)NH * NG];               // [i][c] = W_hh[c][i]
__device__ unsigned g_flag[NFLAG];                    // per-8-step completion counters

// ---------------- helpers ----------------
__device__ __forceinline__ float ex2f(float x) {
    float r; asm("ex2.approx.f32 %0, %1;" : "=f"(r) : "f"(x)); return r;
}
__device__ __forceinline__ float rcpf(float x) {
    float r; asm("rcp.approx.f32 %0, %1;" : "=f"(r) : "f"(x)); return r;
}
__device__ __forceinline__ float sigf(float x) {
    return rcpf(1.0f + ex2f(-1.4426950408889634f * x));
}
__device__ __forceinline__ float tanh_fast(float x) {
    float e = ex2f(2.8853900817779268f * x);   // e^{2x}
    return 1.0f - 2.0f * rcpf(e + 1.0f);
}
__device__ __forceinline__ unsigned long long pack2(float lo, float hi) {
    unsigned long long r;
    asm("mov.b64 %0, {%1,%2};" : "=l"(r)
        : "r"(__float_as_uint(lo)), "r"(__float_as_uint(hi)));
    return r;
}
__device__ __forceinline__ void unpack2(unsigned long long v, float& lo, float& hi) {
    unsigned a, b;
    asm("mov.b64 {%0,%1}, %2;" : "=r"(a), "=r"(b) : "l"(v));
    lo = __uint_as_float(a); hi = __uint_as_float(b);
}
__device__ __forceinline__ void ffma2(unsigned long long& acc,
                                      unsigned long long a, unsigned long long b) {
    asm("fma.rn.f32x2 %0, %1, %2, %0;" : "+l"(acc) : "l"(a), "l"(b));
}
__device__ __forceinline__ unsigned long long addf2(unsigned long long a,
                                                    unsigned long long b) {
    unsigned long long r;
    asm("add.rn.f32x2 %0, %1, %2;" : "=l"(r) : "l"(a), "l"(b));
    return r;
}
__device__ __forceinline__ unsigned ld_acquire(const unsigned* p) {
    unsigned v;
    asm volatile("ld.acquire.gpu.global.b32 %0, [%1];" : "=r"(v) : "l"(p));
    return v;
}
__device__ __forceinline__ void red_add_release(unsigned* p, unsigned v) {
    asm volatile("red.release.gpu.global.add.u32 [%0], %1;" :: "l"(p), "r"(v));
}

// ---------------- init: zero flags + transpose W_hh ----------------
__global__ void __launch_bounds__(256) init_kernel(const float* __restrict__ W_hh) {
    int t = blockIdx.x * 256 + threadIdx.x;
    if (t < NFLAG) g_flag[t] = 0u;
    for (int o = t; o < NH * NG; o += gridDim.x * 256) {
        int i = o / NG, c = o - i * NG;
        g_wT[o] = W_hh[(size_t)c * NH + i];
    }
}

// ---------------- Phase A: ih = x @ W_ih^T + b_ih ----------------
// CTA tile 128(m) x 64(n), 256 threads, K in 4 chunks of 32.
__global__ void __launch_bounds__(256) ih_gemm_kernel(
    const float* __restrict__ x, const float* __restrict__ W_ih,
    const float* __restrict__ b_ih)
{
    __shared__ __align__(16) float As[128 * 32];   // [m][k]
    __shared__ __align__(16) float Bs[32 * 64];    // [k][n]
    const int m0 = blockIdx.x * 128;
    const int n0 = blockIdx.y * 64;
    const int tid = threadIdx.x;
    const int tx = tid & 7;
    const int ty = tid >> 3;

    unsigned long long acc[4][4];
#pragma unroll
    for (int a = 0; a < 4; a++)
#pragma unroll
        for (int c = 0; c < 4; c++) acc[a][c] = 0ull;

    const float4* x4 = (const float4*)x;
    const float4* w4 = (const float4*)W_ih;
    const int lm = tid >> 3;
    const int lk = tid & 7;

    float4 ra[4], rb[2];
#define LOAD_CHUNK(kc)                                                          \
    {                                                                           \
        _Pragma("unroll")                                                       \
        for (int r = 0; r < 4; r++)                                             \
            ra[r] = x4[(size_t)(m0 + lm + r * 32) * 32 + (kc) * 8 + lk];        \
        _Pragma("unroll")                                                       \
        for (int r = 0; r < 2; r++) {                                           \
            int idx = tid + r * 256;                                            \
            rb[r] = w4[(size_t)(n0 + (idx >> 3)) * 32 + (kc) * 8 + (idx & 7)];  \
        }                                                                       \
    }

    LOAD_CHUNK(0);
#pragma unroll
    for (int kc = 0; kc < 4; kc++) {
        __syncthreads();
#pragma unroll
        for (int r = 0; r < 4; r++)
            ((float4*)As)[(lm + r * 32) * 8 + lk] = ra[r];
#pragma unroll
        for (int r = 0; r < 2; r++) {
            int idx = tid + r * 256;
            int n = idx >> 3, kq = idx & 7;
            Bs[(kq * 4 + 0) * 64 + n] = rb[r].x;
            Bs[(kq * 4 + 1) * 64 + n] = rb[r].y;
            Bs[(kq * 4 + 2) * 64 + n] = rb[r].z;
            Bs[(kq * 4 + 3) * 64 + n] = rb[r].w;
        }
        __syncthreads();
        if (kc < 3) LOAD_CHUNK(kc + 1);
#pragma unroll 8
        for (int k = 0; k < 32; k++) {
            unsigned long long a2[4];
#pragma unroll
            for (int mm = 0; mm < 4; mm++) {
                float av = As[(ty * 4 + mm) * 32 + k];
                a2[mm] = pack2(av, av);
            }
            const ulonglong2* bp = (const ulonglong2*)(Bs + k * 64 + tx * 8);
            ulonglong2 p0 = bp[0], p1 = bp[1];
            unsigned long long b2[4] = {p0.x, p0.y, p1.x, p1.y};
#pragma unroll
            for (int mm = 0; mm < 4; mm++)
#pragma unroll
                for (int c = 0; c < 4; c++)
                    ffma2(acc[mm][c], a2[mm], b2[c]);
        }
    }
#undef LOAD_CHUNK
#pragma unroll
    for (int mm = 0; mm < 4; mm++) {
        int m = m0 + ty * 4 + mm;
        float* orow = g_ih + (size_t)m * NG + n0 + tx * 8;
        float vals[8];
#pragma unroll
        for (int c = 0; c < 4; c++) {
            float lo, hi;
            unpack2(acc[mm][c], lo, hi);
            int n = n0 + tx * 8 + c * 2;
            vals[c * 2]     = lo + b_ih[n];
            vals[c * 2 + 1] = hi + b_ih[n + 1];
        }
        ((float4*)orow)[0] = make_float4(vals[0], vals[1], vals[2], vals[3]);
        ((float4*)orow)[1] = make_float4(vals[4], vals[5], vals[6], vals[7]);
    }
}

// ---------------- Mega kernel: scan producers + jac consumers ----------------
__global__ void __launch_bounds__(384, 1) mega_kernel(
    const float* __restrict__ W_hh, const float* __restrict__ b_hh,
    const float* __restrict__ W_y,  const float* __restrict__ b_y,
    float* __restrict__ out)
{
    const int tid = threadIdx.x;

    if (blockIdx.x < NB) {
        // ================= PRODUCER: GRU scan for batch b =================
        const int b = blockIdx.x;
        const int g = tid;
        const int role = g >> 7;        // 0: r, 1: z, 2: n (warp-uniform)
        const int j = g & 127;

        __shared__ __align__(16) float h_sh[NH];
        __shared__ __align__(8) float2 rp_sh[NH];   // (r, r*(1-r))
        __shared__ __align__(8) float2 zp_sh[NH];   // (z, z*(1-z))

        unsigned long long w2[64];
        const unsigned long long* wrow =
            (const unsigned long long*)(W_hh + (size_t)g * NH);
#pragma unroll
        for (int k2 = 0; k2 < 64; k2++) w2[k2] = wrow[k2];
        const float bh = b_hh[g];

        if (g < NH) h_sh[g] = 0.0f;

        const float* ihp = g_ih + (size_t)b * NS * NG;
        float ih_next = ihp[g];
        __syncthreads();

        for (int s = 0; s < NS; s++) {
            float ih_cur = ih_next;
            if (s + 1 < NS) ih_next = ihp[(size_t)(s + 1) * NG + g];

            // hh[g] = W_hh[g,:] . h + b_hh[g]  (f32x2)
            unsigned long long acc[4] = {0ull, 0ull, 0ull, 0ull};
            const ulonglong2* h4 = (const ulonglong2*)h_sh;
#pragma unroll
            for (int k4 = 0; k4 < 32; k4++) {
                ulonglong2 hv = h4[k4];
                ffma2(acc[(2 * k4) & 3],     w2[2 * k4],     hv.x);
                ffma2(acc[(2 * k4 + 1) & 3], w2[2 * k4 + 1], hv.y);
            }
            unsigned long long t01 = addf2(acc[0], acc[1]);
            unsigned long long t23 = addf2(acc[2], acc[3]);
            unsigned long long tt  = addf2(t01, t23);
            float lo, hi;
            unpack2(tt, lo, hi);
            float sum = lo + hi + bh;

            const size_t cb = ((size_t)(s * NB + b)) * (4 * NH);
            if (role == 0) {
                float r = sigf(ih_cur + sum);
                rp_sh[j] = make_float2(r, r * (1.0f - r));
                asm volatile("bar.arrive 1, 384;" ::: "memory");
            } else if (role == 1) {
                float z = sigf(ih_cur + sum);
                zp_sh[j] = make_float2(z, z * (1.0f - z));
                g_coef[cb + 3 * NH + j] = z;
                asm volatile("bar.arrive 1, 384;" ::: "memory");
            } else {
                float M = sum;
                float hp = h_sh[j];                 // own slot, pre-sync safe
                asm volatile("bar.sync 1, 384;" ::: "memory");
                float2 rp = rp_sh[j];
                float2 zp = zp_sh[j];
                float n = tanh_fast(ih_cur + rp.x * M);
                float c67 = (1.0f - n * n) * (1.0f - zp.x);
                g_coef[cb + j]          = rp.y * M * c67;     // cr
                g_coef[cb + NH + j]     = rp.x * c67;         // cn
                g_coef[cb + 2 * NH + j] = zp.y * (hp - n);    // cz
                h_sh[j] = n + zp.x * (hp - n);                // h_new
            }
            __syncthreads();
            // release: coef stores happen-before this bar; red.release gives
            // consumers' acquire loads transitive visibility. No MEMBAR needed.
            if (tid == 0 && (s & (FLAG_STEP - 1)) == FLAG_STEP - 1)
                red_add_release(&g_flag[s >> 3], 1u);
        }

        // y = h_last @ W_y^T + b_y
        if (g < NO) {
            float a = b_y[g];
            const float* wy = W_y + (size_t)g * NH;
#pragma unroll
            for (int k = 0; k < NH; k++) a = fmaf(wy[k], h_sh[k], a);
            out[b * NO + g] = a;
        }
    } else {
        // ========== CONSUMER: Jacobian, dual-b tiles (W loaded once/pair) ==========
        const int c0 = blockIdx.x - NB;     // 0..115
        const int w = tid >> 5;             // warp 0..11 -> i rows
        const int lane = tid & 31;
        const int j0 = lane * 4;
        float* jac = out + NB * NO;

        int scready = -1;
        for (int t = c0; t < NS * 16; t += NCONS) {
            int s = t >> 4;
            int b0 = t & 15;                // pair: (s, b0) and (s, b0+16)
            int sc = s >> 3;
            if (sc != scready) {
                if (tid == 0) {
                    while (ld_acquire(&g_flag[sc]) < (unsigned)NB) __nanosleep(128);
                }
                __syncthreads();
                scready = sc;
            }
            const float4* cpA = (const float4*)(g_coef + (size_t)(s * NB + b0) * (4 * NH));
            const float4* cpB = (const float4*)(g_coef + (size_t)(s * NB + b0 + 16) * (4 * NH));
            float4 crA = cpA[lane], cnA = cpA[32 + lane], czA = cpA[64 + lane], zzA = cpA[96 + lane];
            float4 crB = cpB[lane], cnB = cpB[32 + lane], czB = cpB[64 + lane], zzB = cpB[96 + lane];
            float* obA = jac + ((size_t)((NS - 1 - s) * NB + b0)) * (NH * NH);
            float* obB = jac + ((size_t)((NS - 1 - s) * NB + b0 + 16)) * (NH * NH);
            for (int i = w; i < NH; i += 12) {
                const float4* wp = (const float4*)(g_wT + (size_t)i * NG);
                float4 wr = wp[lane];          // W_hh[j, i]
                float4 wz = wp[32 + lane];     // W_hh[H+j, i]
                float4 wn = wp[64 + lane];     // W_hh[2H+j, i]
                float4 vA, vB;
                vA.x = fmaf(wr.x, crA.x, fmaf(wn.x, cnA.x, wz.x * czA.x));
                vA.y = fmaf(wr.y, crA.y, fmaf(wn.y, cnA.y, wz.y * czA.y));
                vA.z = fmaf(wr.z, crA.z, fmaf(wn.z, cnA.z, wz.z * czA.z));
                vA.w = fmaf(wr.w, crA.w, fmaf(wn.w, cnA.w, wz.w * czA.w));
                vB.x = fmaf(wr.x, crB.x, fmaf(wn.x, cnB.x, wz.x * czB.x));
                vB.y = fmaf(wr.y, crB.y, fmaf(wn.y, cnB.y, wz.y * czB.y));
                vB.z = fmaf(wr.z, crB.z, fmaf(wn.z, cnB.z, wz.z * czB.z));
                vB.w = fmaf(wr.w, crB.w, fmaf(wn.w, cnB.w, wz.w * czB.w));
                if ((i >> 2) == lane) {        // diagonal j == i
                    int d = i & 3;
                    if (d == 0) { vA.x += zzA.x; vB.x += zzB.x; }
                    else if (d == 1) { vA.y += zzA.y; vB.y += zzB.y; }
                    else if (d == 2) { vA.z += zzA.z; vB.z += zzB.z; }
                    else { vA.w += zzA.w; vB.w += zzB.w; }
                }
                *(float4*)(obA + i * NH + j0) = vA;
                *(float4*)(obB + i * NH + j0) = vB;
            }
        }
    }
}

// ---------------- launch ----------------
extern "C" void kernel_launch(void* const* d_in, const int* in_sizes, int n_in,
                              void* d_out, int out_size) {
    const float* x    = (const float*)d_in[0];
    const float* W_ih = (const float*)d_in[1];
    const float* W_hh = (const float*)d_in[2];
    const float* b_ih = (const float*)d_in[3];
    const float* b_hh = (const float*)d_in[4];
    const float* W_y  = (const float*)d_in[5];
    const float* b_y  = (const float*)d_in[6];
    float* out = (float*)d_out;

    init_kernel<<<64, 256>>>(W_hh);
    ih_gemm_kernel<<<dim3(128, 6), 256>>>(x, W_ih, b_ih);
    mega_kernel<<<NB + NCONS, NG>>>(W_hh, b_hh, W_y, b_y, out);
}